// round 10
// baseline (speedup 1.0000x reference)
#include <cuda_runtime.h>
#include <cstdint>

// ---------------- problem constants ----------------
#define NB   1024
#define H1   28
#define W1   28
#define HW1  784
#define H2   14
#define W2c  14
#define HW2  196
#define C1   32
#define C2   64
#define K2D  288      // 32*9
#define FCK  12544    // 64*196
#define FCN  128
#define SPLITK 16
#define KCHUNK 784

// ---------------- f32x2 packed math ----------------
#define PK2(d, x, y)  asm("mov.b64 %0, {%1,%2};" : "=l"(d) : "f"(x), "f"(y))
#define UPK2(x, y, d) asm("mov.b64 {%0,%1}, %2;" : "=f"(x), "=f"(y) : "l"(d))
#define FMA2(c, a, b) asm("fma.rn.f32x2 %0, %1, %2, %0;" : "+l"(c) : "l"(a), "l"(b))

// ---------------- device scratch ----------------
__device__ float  g_h1  [(size_t)NB * C1 * HW2];
__device__ float  g_off2[(size_t)NB * 18 * HW2];
__device__ float2 g_w2kd[9 * C1 * C2];                   // [kt][c][n] duplicated (w,w)
__device__ float  g_fw1r[(size_t)FCN * FCK];             // [n][hw*64+c]
__device__ float  g_h2  [(size_t)NB * HW2 * C2];         // [(b*196+hw)][c]  (m-major)
__device__ float  g_a1p [(size_t)SPLITK * NB * FCN];
__device__ float  g_a1  [(size_t)NB * FCN];

// deform2 dynamic smem: sh1(32*197) + 2*ss(32*200) + 2*sw(32*64 float2)
#define D2_F32S (32 * 197 + 2 * 32 * 200 + 2 * 32 * 64 * 2)
#define D2_SMEM (D2_F32S * 4)

// ---------------- helpers ----------------
__device__ __forceinline__ float bilin(const float* __restrict__ img, int H, int W,
                                       float py, float px) {
    float y0f = floorf(py), x0f = floorf(px);
    int y0 = (int)y0f, x0 = (int)x0f;
    float wy1 = py - y0f, wx1 = px - x0f;
    float wy0 = 1.f - wy1, wx0 = 1.f - wx1;
    bool yv0 = (y0 >= 0) && (y0 < H);
    bool yv1 = (y0 >= -1) && (y0 < H - 1);
    bool xv0 = (x0 >= 0) && (x0 < W);
    bool xv1 = (x0 >= -1) && (x0 < W - 1);
    int yc0 = min(max(y0, 0), H - 1),   yc1 = min(max(y0 + 1, 0), H - 1);
    int xc0 = min(max(x0, 0), W - 1),   xc1 = min(max(x0 + 1, 0), W - 1);
    float v = 0.f;
    v += (yv0 && xv0) ? wy0 * wx0 * img[yc0 * W + xc0] : 0.f;
    v += (yv0 && xv1) ? wy0 * wx1 * img[yc0 * W + xc1] : 0.f;
    v += (yv1 && xv0) ? wy1 * wx0 * img[yc1 * W + xc0] : 0.f;
    v += (yv1 && xv1) ? wy1 * wx1 * img[yc1 * W + xc1] : 0.f;
    return v;
}

// ---------------- K0: weight rearranges ----------------
__global__ void k_prep(const float* __restrict__ w2, const float* __restrict__ fw1) {
    int t = blockIdx.x * blockDim.x + threadIdx.x;
    if (t < 9 * C1 * C2) {
        int kt = t / (C1 * C2), r = t % (C1 * C2), c = r / C2, n = r % C2;
        float w = w2[n * K2D + c * 9 + kt];
        g_w2kd[t] = make_float2(w, w);
    }
    int stride = gridDim.x * blockDim.x;
    for (int i = t; i < FCN * FCK; i += stride) {
        int n = i / FCK, r = i % FCK, hw = r / 64, c = r % 64;
        g_fw1r[i] = fw1[(size_t)n * FCK + c * HW2 + hw];
    }
}

// ---------------- K1: fused offset-conv1 + deform-conv1 + relu + pool ----------------
__global__ void __launch_bounds__(224) k_deform1(const float* __restrict__ x,
                                                 const float* __restrict__ ow1,
                                                 const float* __restrict__ ob1,
                                                 const float* __restrict__ w1,
                                                 const float* __restrict__ b1) {
    int b = blockIdx.x;
    __shared__ float sx[HW1];
    __shared__ float sow[162];
    __shared__ float sob[18];
    __shared__ float swt[C1 * 9];
    __shared__ float sb[C1];
    for (int i = threadIdx.x; i < HW1; i += 224) sx[i] = x[(size_t)b * HW1 + i];
    if (threadIdx.x < 162) sow[threadIdx.x] = ow1[threadIdx.x];
    if (threadIdx.x < 18)  sob[threadIdx.x] = ob1[threadIdx.x];
    for (int i = threadIdx.x; i < C1 * 9; i += 224) swt[i] = w1[i];
    if (threadIdx.x < C1) sb[threadIdx.x] = b1[threadIdx.x];
    __syncthreads();
    int t = threadIdx.x;
    if (t >= HW2) return;
    int ph = t / W2c, pw = t % W2c;
    float acc[C1];
#pragma unroll
    for (int o = 0; o < C1; o++) acc[o] = 0.f;
#pragma unroll 1
    for (int s4 = 0; s4 < 4; s4++) {
        int y = ph * 2 + (s4 >> 1), w = pw * 2 + (s4 & 1);
        float p[9];
#pragma unroll
        for (int ky = 0; ky < 3; ky++)
#pragma unroll
            for (int kx = 0; kx < 3; kx++) {
                int y2 = y + ky - 1, x2 = w + kx - 1;
                bool ok = (y2 >= 0) && (y2 < H1) && (x2 >= 0) && (x2 < W1);
                p[ky * 3 + kx] = ok ? sx[y2 * W1 + x2] : 0.f;
            }
        float s[9];
#pragma unroll
        for (int k = 0; k < 9; k++) {
            float dy = sob[2 * k], dx = sob[2 * k + 1];
#pragma unroll
            for (int j = 0; j < 9; j++) {
                dy += sow[(2 * k) * 9 + j] * p[j];
                dx += sow[(2 * k + 1) * 9 + j] * p[j];
            }
            int ky = k / 3, kx = k % 3;
            s[k] = bilin(sx, H1, W1, dy + (float)(y - 1 + ky), dx + (float)(w - 1 + kx));
        }
#pragma unroll
        for (int o = 0; o < C1; o++) {
            float v = sb[o];
#pragma unroll
            for (int k = 0; k < 9; k++) v += swt[o * 9 + k] * s[k];
            acc[o] += fmaxf(v, 0.f);
        }
    }
#pragma unroll
    for (int o = 0; o < C1; o++)
        g_h1[((size_t)b * C1 + o) * HW2 + t] = acc[o] * 0.25f;
}

// ---------------- K2: offset conv2 ----------------
__global__ void __launch_bounds__(192) k_offset2(const float* __restrict__ ow2,
                                                 const float* __restrict__ ob2) {
    int b = blockIdx.x;
    __shared__ float sh[16 * 256];
    __shared__ float sw[18 * 144];
    int t = threadIdx.x;
    bool act = t < 168;
    int og = t / 28, pg = t % 28;
    int y = pg >> 1, x0 = (pg & 1) * 7;
    int o0 = og * 3;
    float acc[3][7];
    if (act) {
#pragma unroll
        for (int q = 0; q < 3; q++) {
            float bv = ob2[o0 + q];
#pragma unroll
            for (int p = 0; p < 7; p++) acc[q][p] = bv;
        }
    }
#pragma unroll 1
    for (int half = 0; half < 2; half++) {
        if (half) __syncthreads();
        for (int i = t; i < 16 * 60; i += 192) {
            int c = i / 60, e = i % 60;
            int py, px;
            if (e < 16)      { py = 0;  px = e; }
            else if (e < 32) { py = 15; px = e - 16; }
            else { int e2 = e - 32; py = 1 + (e2 >> 1); px = (e2 & 1) * 15; }
            sh[c * 256 + py * 16 + px] = 0.f;
        }
        for (int i = t; i < 16 * HW2; i += 192) {
            int c = i / HW2, hw = i % HW2, yy = hw / W2c, xx = hw % W2c;
            sh[c * 256 + (yy + 1) * 16 + (xx + 1)] =
                g_h1[(size_t)b * (C1 * HW2) + (half * 16 + c) * HW2 + hw];
        }
        for (int i = t; i < 18 * 144; i += 192) {
            int o = i / 144, r = i % 144, cl = r / 9, kt = r % 9;
            sw[i] = ow2[o * K2D + (half * 16 + cl) * 9 + kt];
        }
        __syncthreads();
        if (act) {
#pragma unroll 1
            for (int c = 0; c < 16; c++) {
                const float* base = &sh[c * 256 + y * 16 + x0];
                float nb[27];
#pragma unroll
                for (int dy = 0; dy < 3; dy++)
#pragma unroll
                    for (int dx = 0; dx < 9; dx++)
                        nb[dy * 9 + dx] = base[dy * 16 + dx];
#pragma unroll
                for (int kt = 0; kt < 9; kt++) {
                    int ky = kt / 3, kx = kt % 3;
                    float w0 = sw[(o0 + 0) * 144 + c * 9 + kt];
                    float w1v = sw[(o0 + 1) * 144 + c * 9 + kt];
                    float w2v = sw[(o0 + 2) * 144 + c * 9 + kt];
#pragma unroll
                    for (int p = 0; p < 7; p++) {
                        float v = nb[ky * 9 + kx + p];
                        acc[0][p] += w0 * v;
                        acc[1][p] += w1v * v;
                        acc[2][p] += w2v * v;
                    }
                }
            }
        }
    }
    if (act) {
#pragma unroll
        for (int q = 0; q < 3; q++)
#pragma unroll
            for (int p = 0; p < 7; p++)
                g_off2[((size_t)b * 18 + o0 + q) * HW2 + y * W2c + x0 + p] = acc[q][p];
    }
}

// ---------------- K3: FUSED sampling + deform2 GEMM (v5) -------------------
// 200 threads: ty=tid/8 (25 m-groups of 8), tx=tid%8 (8 n-groups of 8).
// Ping-pong ss/sw buffers; pre-duplicated weights; 10 barriers total.
__global__ void __launch_bounds__(200) k_deform2(const float* __restrict__ b2) {
    extern __shared__ float dsm[];
    float*  sh1 = dsm;                               // 32 x 197
    float*  ss  = dsm + 32 * 197;                    // 2 x (32 x 200)
    float2* sw2 = (float2*)(dsm + 32 * 197 + 2 * 32 * 200);  // 2 x (32 x 64) pairs
    int b = blockIdx.x;
    int tid = threadIdx.x;
    for (int i = tid; i < C1 * HW2; i += 200) {
        int c = i / HW2, hw = i % HW2;
        sh1[c * 197 + hw] = g_h1[(size_t)b * (C1 * HW2) + i];
    }
    int ty = tid >> 3, tx = tid & 7;
    bool samp_act = tid < HW2;
    int shw = tid, sy = shw / W2c, sx = shw % W2c;

    unsigned long long accp[4][8];
#pragma unroll
    for (int i = 0; i < 4; i++)
#pragma unroll
        for (int j = 0; j < 8; j++) accp[i][j] = 0ull;

    float w00 = 0.f, w01 = 0.f, w10 = 0.f, w11 = 0.f;
    int i00 = 0, i01 = 0, i10 = 0, i11 = 0;
    // --- bilinear params for a tap (registers only) ---
#define D2_PARAMS(KT)                                                          \
    if (samp_act) {                                                            \
        int ky = (KT) / 3, kx = (KT) % 3;                                      \
        float dy = g_off2[((size_t)b * 18 + 2 * (KT))     * HW2 + shw];        \
        float dx = g_off2[((size_t)b * 18 + 2 * (KT) + 1) * HW2 + shw];        \
        float py = dy + (float)(sy - 1 + ky);                                  \
        float px = dx + (float)(sx - 1 + kx);                                  \
        float y0f = floorf(py), x0f = floorf(px);                              \
        int y0 = (int)y0f, x0 = (int)x0f;                                      \
        float wy1 = py - y0f, wx1 = px - x0f;                                  \
        float wy0 = 1.f - wy1, wx0 = 1.f - wx1;                                \
        bool yv0 = (y0 >= 0) && (y0 < H2), yv1 = (y0 >= -1) && (y0 < H2 - 1);  \
        bool xv0 = (x0 >= 0) && (x0 < W2c), xv1 = (x0 >= -1) && (x0 < W2c - 1);\
        int yc0 = min(max(y0, 0), H2 - 1),  yc1 = min(max(y0 + 1, 0), H2 - 1); \
        int xc0 = min(max(x0, 0), W2c - 1), xc1 = min(max(x0 + 1, 0), W2c - 1);\
        w00 = (yv0 && xv0) ? wy0 * wx0 : 0.f;                                  \
        w01 = (yv0 && xv1) ? wy0 * wx1 : 0.f;                                  \
        w10 = (yv1 && xv0) ? wy1 * wx0 : 0.f;                                  \
        w11 = (yv1 && xv1) ? wy1 * wx1 : 0.f;                                  \
        i00 = yc0 * W2c + xc0; i01 = yc0 * W2c + xc1;                          \
        i10 = yc1 * W2c + xc0; i11 = yc1 * W2c + xc1;                          \
    }
    // --- sample all 32 channels of one tap into buffer, copy its weights ---
#define D2_PRODUCE(KT, BUF)                                                    \
    {                                                                          \
        float* ssb = ss + (BUF) * (32 * 200);                                  \
        if (samp_act) {                                                        \
            _Pragma("unroll 4")                                                \
            for (int c = 0; c < C1; c++) {                                     \
                const float* im = &sh1[c * 197];                               \
                ssb[c * 200 + shw] =                                           \
                    w00 * im[i00] + w01 * im[i01] + w10 * im[i10] + w11 * im[i11]; \
            }                                                                  \
        }                                                                      \
        float2* swb = sw2 + (BUF) * (C1 * C2);                                 \
        for (int i = tid; i < C1 * C2; i += 200)                               \
            swb[i] = g_w2kd[(KT) * (C1 * C2) + i];                             \
    }

    // prologue: fill buffer 0
    D2_PARAMS(0)
    __syncthreads();            // sh1 ready
    D2_PRODUCE(0, 0)
    __syncthreads();            // buffer 0 ready

#pragma unroll 1
    for (int kt = 0; kt < 9; kt++) {
        int cur = kt & 1;
        if (kt < 8) {
            D2_PARAMS(kt + 1)
            D2_PRODUCE(kt + 1, cur ^ 1)   // fill idle buffer (overlaps GEMM below)
        }
        const float*  ssb = ss  + cur * (32 * 200);
        const float2* swb = sw2 + cur * (C1 * C2);
#pragma unroll 8
        for (int c = 0; c < C1; c++) {
            float4 a0 = *(const float4*)&ssb[c * 200 + ty * 8];
            float4 a1 = *(const float4*)&ssb[c * 200 + ty * 8 + 4];
            float4 q0 = *(const float4*)&swb[c * C2 + tx * 8];
            float4 q1 = *(const float4*)&swb[c * C2 + tx * 8 + 2];
            float4 q2 = *(const float4*)&swb[c * C2 + tx * 8 + 4];
            float4 q3 = *(const float4*)&swb[c * C2 + tx * 8 + 6];
            unsigned long long ap[4], bp[8];
            PK2(ap[0], a0.x, a0.y); PK2(ap[1], a0.z, a0.w);
            PK2(ap[2], a1.x, a1.y); PK2(ap[3], a1.z, a1.w);
            PK2(bp[0], q0.x, q0.y); PK2(bp[1], q0.z, q0.w);
            PK2(bp[2], q1.x, q1.y); PK2(bp[3], q1.z, q1.w);
            PK2(bp[4], q2.x, q2.y); PK2(bp[5], q2.z, q2.w);
            PK2(bp[6], q3.x, q3.y); PK2(bp[7], q3.z, q3.w);
#pragma unroll
            for (int i = 0; i < 4; i++)
#pragma unroll
                for (int j = 0; j < 8; j++) FMA2(accp[i][j], ap[i], bp[j]);
        }
        if (kt < 8) __syncthreads();
    }

    // epilogue: bias + relu, store m-major [m][64] (skip padded m >= 196)
    float4 bv0 = *(const float4*)&b2[tx * 8];
    float4 bv1 = *(const float4*)&b2[tx * 8 + 4];
    float r[8][8];
#pragma unroll
    for (int p = 0; p < 4; p++)
#pragma unroll
        for (int j = 0; j < 8; j++) {
            float lo, hi;
            UPK2(lo, hi, accp[p][j]);
            r[2 * p][j] = lo; r[2 * p + 1][j] = hi;
        }
#pragma unroll
    for (int i = 0; i < 8; i++) {
        int m = ty * 8 + i;
        if (m < HW2) {
            float4 v0 = make_float4(fmaxf(r[i][0] + bv0.x, 0.f), fmaxf(r[i][1] + bv0.y, 0.f),
                                    fmaxf(r[i][2] + bv0.z, 0.f), fmaxf(r[i][3] + bv0.w, 0.f));
            float4 v1 = make_float4(fmaxf(r[i][4] + bv1.x, 0.f), fmaxf(r[i][5] + bv1.y, 0.f),
                                    fmaxf(r[i][6] + bv1.z, 0.f), fmaxf(r[i][7] + bv1.w, 0.f));
            float* dst = &g_h2[((size_t)(b * HW2 + m)) * C2 + tx * 8];
            *(float4*)dst = v0;
            *(float4*)(dst + 4) = v1;
        }
    }
#undef D2_PARAMS
#undef D2_PRODUCE
}

// ---------------- fc1 GEMM: BM=128 BN=64 BK=16, 256 thr, 8x4 tile, f32x2 ----------------
__global__ void __launch_bounds__(256) k_gemm1(int lda, int k_chunk, int k_iters) {
    const float* __restrict__ A  = g_h2;
    const float* __restrict__ Bw = g_fw1r;
    __shared__ __align__(16) float As[2][16][132];
    __shared__ __align__(16) float Bs[2][16][68];
    int m0 = blockIdx.x * 128, n0 = blockIdx.y * 64;
    int kbase = blockIdx.z * k_chunk;
    int tid = threadIdx.x;
    int ty = tid >> 4, tx = tid & 15;
    int am = tid >> 2, aq = tid & 3;
    const float* Ap0 = &A[(size_t)(m0 + am)      * lda + kbase + aq * 4];
    const float* Ap1 = &A[(size_t)(m0 + am + 64) * lda + kbase + aq * 4];
    const float* Bp  = &Bw[(size_t)(n0 + am)     * lda + kbase + aq * 4];
    unsigned long long accp[4][4];
#pragma unroll
    for (int i = 0; i < 4; i++)
#pragma unroll
        for (int j = 0; j < 4; j++) accp[i][j] = 0ull;

    float4 va0 = *(const float4*)Ap0;
    float4 va1 = *(const float4*)Ap1;
    float4 vb  = *(const float4*)Bp;
#pragma unroll 1
    for (int t = 0; t < k_iters; t++) {
        int cur = t & 1;
        As[cur][aq * 4 + 0][am] = va0.x; As[cur][aq * 4 + 1][am] = va0.y;
        As[cur][aq * 4 + 2][am] = va0.z; As[cur][aq * 4 + 3][am] = va0.w;
        As[cur][aq * 4 + 0][am + 64] = va1.x; As[cur][aq * 4 + 1][am + 64] = va1.y;
        As[cur][aq * 4 + 2][am + 64] = va1.z; As[cur][aq * 4 + 3][am + 64] = va1.w;
        Bs[cur][aq * 4 + 0][am] = vb.x; Bs[cur][aq * 4 + 1][am] = vb.y;
        Bs[cur][aq * 4 + 2][am] = vb.z; Bs[cur][aq * 4 + 3][am] = vb.w;
        __syncthreads();
        if (t + 1 < k_iters) {
            va0 = *(const float4*)(Ap0 + (t + 1) * 16);
            va1 = *(const float4*)(Ap1 + (t + 1) * 16);
            vb  = *(const float4*)(Bp  + (t + 1) * 16);
        }
#pragma unroll
        for (int k = 0; k < 16; k++) {
            float4 a0 = *(const float4*)&As[cur][k][ty * 8];
            float4 a1 = *(const float4*)&As[cur][k][ty * 8 + 4];
            float4 b0 = *(const float4*)&Bs[cur][k][tx * 4];
            unsigned long long ap[4], bp[4];
            PK2(ap[0], a0.x, a0.y); PK2(ap[1], a0.z, a0.w);
            PK2(ap[2], a1.x, a1.y); PK2(ap[3], a1.z, a1.w);
            PK2(bp[0], b0.x, b0.x); PK2(bp[1], b0.y, b0.y);
            PK2(bp[2], b0.z, b0.z); PK2(bp[3], b0.w, b0.w);
#pragma unroll
            for (int i = 0; i < 4; i++)
#pragma unroll
                for (int j = 0; j < 4; j++) FMA2(accp[i][j], ap[i], bp[j]);
        }
        if (t + 1 < k_iters) __syncthreads();
    }

    float r[8][4];
#pragma unroll
    for (int p = 0; p < 4; p++)
#pragma unroll
        for (int j = 0; j < 4; j++) {
            float lo, hi;
            UPK2(lo, hi, accp[p][j]);
            r[2 * p][j] = lo; r[2 * p + 1][j] = hi;
        }
#pragma unroll
    for (int i = 0; i < 8; i++) {
        int m = m0 + ty * 8 + i;
        float4 v = make_float4(r[i][0], r[i][1], r[i][2], r[i][3]);
        *(float4*)&g_a1p[((size_t)blockIdx.z * NB + m) * FCN + n0 + tx * 4] = v;
    }
}

// ---------------- reduce split-K + bias + relu ----------------
__global__ void __launch_bounds__(256) k_fc1fin(const float* __restrict__ fb1) {
    int t = blockIdx.x * blockDim.x + threadIdx.x;
    if (t >= NB * FCN) return;
    int n = t & (FCN - 1);
    float s = fb1[n];
#pragma unroll
    for (int z = 0; z < SPLITK; z++) s += g_a1p[(size_t)z * NB * FCN + t];
    g_a1[t] = fmaxf(s, 0.f);
}

// ---------------- fc2 ----------------
__global__ void __launch_bounds__(256) k_fc2(const float* __restrict__ fw2,
                                             const float* __restrict__ fb2,
                                             float* __restrict__ out) {
    int t = blockIdx.x * blockDim.x + threadIdx.x;
    if (t >= NB * 10) return;
    int b = t / 10, o = t % 10;
    float s = fb2[o];
    const float* a = &g_a1[(size_t)b * FCN];
    const float* w = &fw2[(size_t)o * FCN];
#pragma unroll 16
    for (int j = 0; j < FCN; j++) s += a[j] * w[j];
    out[t] = s;
}

// ---------------- launch ----------------
extern "C" void kernel_launch(void* const* d_in, const int* in_sizes, int n_in,
                              void* d_out, int out_size) {
    const float* x   = (const float*)d_in[0];
    const float* ow1 = (const float*)d_in[1];
    const float* ob1 = (const float*)d_in[2];
    const float* w1  = (const float*)d_in[3];
    const float* b1  = (const float*)d_in[4];
    const float* ow2 = (const float*)d_in[5];
    const float* ob2 = (const float*)d_in[6];
    const float* w2  = (const float*)d_in[7];
    const float* b2  = (const float*)d_in[8];
    const float* fw1 = (const float*)d_in[9];
    const float* fb1 = (const float*)d_in[10];
    const float* fw2 = (const float*)d_in[11];
    const float* fb2 = (const float*)d_in[12];
    float* out = (float*)d_out;
    (void)in_sizes; (void)n_in; (void)out_size;

    static int configured = 0;
    if (!configured) {
        cudaFuncSetAttribute(k_deform2, cudaFuncAttributeMaxDynamicSharedMemorySize, D2_SMEM);
        configured = 1;
    }

    k_prep<<<784, 256>>>(w2, fw1);
    k_deform1<<<NB, 224>>>(x, ow1, ob1, w1, b1);
    k_offset2<<<NB, 192>>>(ow2, ob2);
    k_deform2<<<NB, 200, D2_SMEM>>>(b2);
    k_gemm1<<<dim3(8, 2, SPLITK), 256>>>(FCK, KCHUNK, KCHUNK / 16);
    k_fc1fin<<<(NB * FCN) / 256, 256>>>(fb1);
    k_fc2<<<(NB * 10 + 255) / 256, 256>>>(fw2, fb2, out);
}

// round 11
// speedup vs baseline: 1.3218x; 1.3218x over previous
#include <cuda_runtime.h>
#include <cstdint>

// ---------------- problem constants ----------------
#define NB   1024
#define H1   28
#define W1   28
#define HW1  784
#define H2   14
#define W2c  14
#define HW2  196
#define C1   32
#define C2   64
#define K2D  288      // 32*9
#define FCK  12544    // 64*196
#define FCN  128
#define SPLITK 16
#define KCHUNK 784

// ---------------- f32x2 packed math ----------------
#define PK2(d, x, y)  asm("mov.b64 %0, {%1,%2};" : "=l"(d) : "f"(x), "f"(y))
#define UPK2(x, y, d) asm("mov.b64 {%0,%1}, %2;" : "=f"(x), "=f"(y) : "l"(d))
#define FMA2(c, a, b) asm("fma.rn.f32x2 %0, %1, %2, %0;" : "+l"(c) : "l"(a), "l"(b))

// ---------------- device scratch ----------------
__device__ float g_h1  [(size_t)NB * C1 * HW2];
__device__ float g_off2[(size_t)NB * 18 * HW2];
__device__ float g_w2k [9 * C1 * C2];                    // [kt][c][n]
__device__ float g_fw1r[(size_t)FCN * FCK];              // [n][hw*64+c]
__device__ float g_h2  [(size_t)NB * HW2 * C2];          // [(b*196+hw)][c]  (m-major)
__device__ float g_a1p [(size_t)SPLITK * NB * FCN];
__device__ float g_a1  [(size_t)NB * FCN];

// deform2 dynamic smem: sh1(32*197) + 2*ss(32*197) + 2*sw(32*68)
#define D2_F32S (32 * 197 + 2 * 32 * 197 + 2 * 32 * 68)
#define D2_SMEM (D2_F32S * 4)

// ---------------- helpers ----------------
__device__ __forceinline__ float bilin(const float* __restrict__ img, int H, int W,
                                       float py, float px) {
    float y0f = floorf(py), x0f = floorf(px);
    int y0 = (int)y0f, x0 = (int)x0f;
    float wy1 = py - y0f, wx1 = px - x0f;
    float wy0 = 1.f - wy1, wx0 = 1.f - wx1;
    bool yv0 = (y0 >= 0) && (y0 < H);
    bool yv1 = (y0 >= -1) && (y0 < H - 1);
    bool xv0 = (x0 >= 0) && (x0 < W);
    bool xv1 = (x0 >= -1) && (x0 < W - 1);
    int yc0 = min(max(y0, 0), H - 1),   yc1 = min(max(y0 + 1, 0), H - 1);
    int xc0 = min(max(x0, 0), W - 1),   xc1 = min(max(x0 + 1, 0), W - 1);
    float v = 0.f;
    v += (yv0 && xv0) ? wy0 * wx0 * img[yc0 * W + xc0] : 0.f;
    v += (yv0 && xv1) ? wy0 * wx1 * img[yc0 * W + xc1] : 0.f;
    v += (yv1 && xv0) ? wy1 * wx0 * img[yc1 * W + xc0] : 0.f;
    v += (yv1 && xv1) ? wy1 * wx1 * img[yc1 * W + xc1] : 0.f;
    return v;
}

// ---------------- K0a: w2 rearrange ----------------
__global__ void k_prep_w2(const float* __restrict__ w2) {
    int t = blockIdx.x * blockDim.x + threadIdx.x;
    if (t < 9 * C1 * C2) {
        int kt = t / (C1 * C2), r = t % (C1 * C2), c = r / C2, n = r % C2;
        g_w2k[t] = w2[n * K2D + c * 9 + kt];
    }
}

// ---------------- K0b: fw1 transpose (coalesced both sides via smem tile) ----------------
// block = (n, half); half covers 98 hw values. smem 64 x 98 padded to stride 99.
__global__ void __launch_bounds__(256) k_prep_fw1(const float* __restrict__ fw1) {
    __shared__ float st[64 * 99];
    int n = blockIdx.x, h0 = blockIdx.y * 98;
    for (int i = threadIdx.x; i < 64 * 98; i += 256) {
        int c = i / 98, hwl = i % 98;
        st[c * 99 + hwl] = fw1[(size_t)n * FCK + c * HW2 + h0 + hwl];
    }
    __syncthreads();
    for (int j = threadIdx.x; j < 98 * 64; j += 256) {
        int hwl = j / 64, c = j % 64;
        g_fw1r[(size_t)n * FCK + (h0 + hwl) * 64 + c] = st[c * 99 + hwl];
    }
}

// ---------------- K1: fused offset-conv1 + deform-conv1 + relu + pool ----------------
__global__ void __launch_bounds__(224) k_deform1(const float* __restrict__ x,
                                                 const float* __restrict__ ow1,
                                                 const float* __restrict__ ob1,
                                                 const float* __restrict__ w1,
                                                 const float* __restrict__ b1) {
    int b = blockIdx.x;
    __shared__ float sx[HW1];
    __shared__ float sow[162];
    __shared__ float sob[18];
    __shared__ float swt[C1 * 9];
    __shared__ float sb[C1];
    for (int i = threadIdx.x; i < HW1; i += 224) sx[i] = x[(size_t)b * HW1 + i];
    if (threadIdx.x < 162) sow[threadIdx.x] = ow1[threadIdx.x];
    if (threadIdx.x < 18)  sob[threadIdx.x] = ob1[threadIdx.x];
    for (int i = threadIdx.x; i < C1 * 9; i += 224) swt[i] = w1[i];
    if (threadIdx.x < C1) sb[threadIdx.x] = b1[threadIdx.x];
    __syncthreads();
    int t = threadIdx.x;
    if (t >= HW2) return;
    int ph = t / W2c, pw = t % W2c;
    float acc[C1];
#pragma unroll
    for (int o = 0; o < C1; o++) acc[o] = 0.f;
#pragma unroll 1
    for (int s4 = 0; s4 < 4; s4++) {
        int y = ph * 2 + (s4 >> 1), w = pw * 2 + (s4 & 1);
        float p[9];
#pragma unroll
        for (int ky = 0; ky < 3; ky++)
#pragma unroll
            for (int kx = 0; kx < 3; kx++) {
                int y2 = y + ky - 1, x2 = w + kx - 1;
                bool ok = (y2 >= 0) && (y2 < H1) && (x2 >= 0) && (x2 < W1);
                p[ky * 3 + kx] = ok ? sx[y2 * W1 + x2] : 0.f;
            }
        float s[9];
#pragma unroll
        for (int k = 0; k < 9; k++) {
            float dy = sob[2 * k], dx = sob[2 * k + 1];
#pragma unroll
            for (int j = 0; j < 9; j++) {
                dy += sow[(2 * k) * 9 + j] * p[j];
                dx += sow[(2 * k + 1) * 9 + j] * p[j];
            }
            int ky = k / 3, kx = k % 3;
            s[k] = bilin(sx, H1, W1, dy + (float)(y - 1 + ky), dx + (float)(w - 1 + kx));
        }
#pragma unroll
        for (int o = 0; o < C1; o++) {
            float v = sb[o];
#pragma unroll
            for (int k = 0; k < 9; k++) v += swt[o * 9 + k] * s[k];
            acc[o] += fmaxf(v, 0.f);
        }
    }
#pragma unroll
    for (int o = 0; o < C1; o++)
        g_h1[((size_t)b * C1 + o) * HW2 + t] = acc[o] * 0.25f;
}

// ---------------- K2: offset conv2 ----------------
__global__ void __launch_bounds__(192) k_offset2(const float* __restrict__ ow2,
                                                 const float* __restrict__ ob2) {
    int b = blockIdx.x;
    __shared__ float sh[16 * 256];
    __shared__ float sw[18 * 144];
    int t = threadIdx.x;
    bool act = t < 168;
    int og = t / 28, pg = t % 28;
    int y = pg >> 1, x0 = (pg & 1) * 7;
    int o0 = og * 3;
    float acc[3][7];
    if (act) {
#pragma unroll
        for (int q = 0; q < 3; q++) {
            float bv = ob2[o0 + q];
#pragma unroll
            for (int p = 0; p < 7; p++) acc[q][p] = bv;
        }
    }
#pragma unroll 1
    for (int half = 0; half < 2; half++) {
        if (half) __syncthreads();
        for (int i = t; i < 16 * 60; i += 192) {
            int c = i / 60, e = i % 60;
            int py, px;
            if (e < 16)      { py = 0;  px = e; }
            else if (e < 32) { py = 15; px = e - 16; }
            else { int e2 = e - 32; py = 1 + (e2 >> 1); px = (e2 & 1) * 15; }
            sh[c * 256 + py * 16 + px] = 0.f;
        }
        for (int i = t; i < 16 * HW2; i += 192) {
            int c = i / HW2, hw = i % HW2, yy = hw / W2c, xx = hw % W2c;
            sh[c * 256 + (yy + 1) * 16 + (xx + 1)] =
                g_h1[(size_t)b * (C1 * HW2) + (half * 16 + c) * HW2 + hw];
        }
        for (int i = t; i < 18 * 144; i += 192) {
            int o = i / 144, r = i % 144, cl = r / 9, kt = r % 9;
            sw[i] = ow2[o * K2D + (half * 16 + cl) * 9 + kt];
        }
        __syncthreads();
        if (act) {
#pragma unroll 1
            for (int c = 0; c < 16; c++) {
                const float* base = &sh[c * 256 + y * 16 + x0];
                float nb[27];
#pragma unroll
                for (int dy = 0; dy < 3; dy++)
#pragma unroll
                    for (int dx = 0; dx < 9; dx++)
                        nb[dy * 9 + dx] = base[dy * 16 + dx];
#pragma unroll
                for (int kt = 0; kt < 9; kt++) {
                    int ky = kt / 3, kx = kt % 3;
                    float w0 = sw[(o0 + 0) * 144 + c * 9 + kt];
                    float w1v = sw[(o0 + 1) * 144 + c * 9 + kt];
                    float w2v = sw[(o0 + 2) * 144 + c * 9 + kt];
#pragma unroll
                    for (int p = 0; p < 7; p++) {
                        float v = nb[ky * 9 + kx + p];
                        acc[0][p] += w0 * v;
                        acc[1][p] += w1v * v;
                        acc[2][p] += w2v * v;
                    }
                }
            }
        }
    }
    if (act) {
#pragma unroll
        for (int q = 0; q < 3; q++)
#pragma unroll
            for (int p = 0; p < 7; p++)
                g_off2[((size_t)b * 18 + o0 + q) * HW2 + y * W2c + x0 + p] = acc[q][p];
    }
}

// ---------------- K3: FUSED sampling + deform2 GEMM (v6) -------------------
// R7 inner body (7m x 8n, scalar a-LDS, 2x b-LDS128, reg dups), but with
// double-buffered ss/sw so produce(kt+1) overlaps GEMM(kt): 10 barriers.
__global__ void __launch_bounds__(224) k_deform2(const float* __restrict__ b2) {
    extern __shared__ float dsm[];
    float* sh1 = dsm;                       // 32 x 197
    float* ss  = dsm + 32 * 197;            // 2 x (32 x 197)
    float* sw  = dsm + 3 * 32 * 197;        // 2 x (32 x 68)
    int b = blockIdx.x;
    int tid = threadIdx.x;
    for (int i = tid; i < C1 * HW2; i += 224) {
        int c = i / HW2, hw = i % HW2;
        sh1[c * 197 + hw] = g_h1[(size_t)b * (C1 * HW2) + i];
    }
    int ty = tid >> 3, tx = tid & 7;
    bool samp_act = tid < HW2;
    int shw = tid, sy = shw / W2c, sx = shw % W2c;

    unsigned long long accp[7][4];
#pragma unroll
    for (int i = 0; i < 7; i++)
#pragma unroll
        for (int j = 0; j < 4; j++) accp[i][j] = 0ull;

    float w00 = 0.f, w01 = 0.f, w10 = 0.f, w11 = 0.f;
    int i00 = 0, i01 = 0, i10 = 0, i11 = 0;
#define D2_PARAMS(KT)                                                          \
    if (samp_act) {                                                            \
        int ky = (KT) / 3, kx = (KT) % 3;                                      \
        float dy = g_off2[((size_t)b * 18 + 2 * (KT))     * HW2 + shw];        \
        float dx = g_off2[((size_t)b * 18 + 2 * (KT) + 1) * HW2 + shw];        \
        float py = dy + (float)(sy - 1 + ky);                                  \
        float px = dx + (float)(sx - 1 + kx);                                  \
        float y0f = floorf(py), x0f = floorf(px);                              \
        int y0 = (int)y0f, x0 = (int)x0f;                                      \
        float wy1 = py - y0f, wx1 = px - x0f;                                  \
        float wy0 = 1.f - wy1, wx0 = 1.f - wx1;                                \
        bool yv0 = (y0 >= 0) && (y0 < H2), yv1 = (y0 >= -1) && (y0 < H2 - 1);  \
        bool xv0 = (x0 >= 0) && (x0 < W2c), xv1 = (x0 >= -1) && (x0 < W2c - 1);\
        int yc0 = min(max(y0, 0), H2 - 1),  yc1 = min(max(y0 + 1, 0), H2 - 1); \
        int xc0 = min(max(x0, 0), W2c - 1), xc1 = min(max(x0 + 1, 0), W2c - 1);\
        w00 = (yv0 && xv0) ? wy0 * wx0 : 0.f;                                  \
        w01 = (yv0 && xv1) ? wy0 * wx1 : 0.f;                                  \
        w10 = (yv1 && xv0) ? wy1 * wx0 : 0.f;                                  \
        w11 = (yv1 && xv1) ? wy1 * wx1 : 0.f;                                  \
        i00 = yc0 * W2c + xc0; i01 = yc0 * W2c + xc1;                          \
        i10 = yc1 * W2c + xc0; i11 = yc1 * W2c + xc1;                          \
    }
#define D2_PRODUCE(KT, BUF)                                                    \
    {                                                                          \
        float* ssb = ss + (BUF) * (32 * 197);                                  \
        if (samp_act) {                                                        \
            _Pragma("unroll 4")                                                \
            for (int c = 0; c < C1; c++) {                                     \
                const float* im = &sh1[c * 197];                               \
                ssb[c * 197 + shw] =                                           \
                    w00 * im[i00] + w01 * im[i01] + w10 * im[i10] + w11 * im[i11]; \
            }                                                                  \
        }                                                                      \
        float* swb = sw + (BUF) * (32 * 68);                                   \
        for (int i = tid; i < C1 * C2; i += 224)                               \
            swb[(i >> 6) * 68 + (i & 63)] = g_w2k[(KT) * (C1 * C2) + i];       \
    }

    // prologue
    D2_PARAMS(0)
    __syncthreads();            // sh1 ready
    D2_PRODUCE(0, 0)
    __syncthreads();            // buffer 0 ready

#pragma unroll 1
    for (int kt = 0; kt < 9; kt++) {
        int cur = kt & 1;
        if (kt < 8) {
            D2_PARAMS(kt + 1)
            D2_PRODUCE(kt + 1, cur ^ 1)   // overlaps with GEMM below via other warps
        }
        const float* ssb = ss + cur * (32 * 197);
        const float* swb = sw + cur * (32 * 68);
#pragma unroll 4
        for (int c = 0; c < C1; c++) {
            float a[7];
#pragma unroll
            for (int i = 0; i < 7; i++) a[i] = ssb[c * 197 + ty * 7 + i];
            float4 b0 = *(const float4*)&swb[c * 68 + tx * 8];
            float4 b1 = *(const float4*)&swb[c * 68 + tx * 8 + 4];
            unsigned long long bp[4], ap;
            PK2(bp[0], b0.x, b0.y); PK2(bp[1], b0.z, b0.w);
            PK2(bp[2], b1.x, b1.y); PK2(bp[3], b1.z, b1.w);
#pragma unroll
            for (int i = 0; i < 7; i++) {
                PK2(ap, a[i], a[i]);
#pragma unroll
                for (int j = 0; j < 4; j++) FMA2(accp[i][j], ap, bp[j]);
            }
        }
        if (kt < 8) __syncthreads();
    }

    // epilogue: bias + relu, store m-major [m][64]
    float4 bv0 = *(const float4*)&b2[tx * 8];
    float4 bv1 = *(const float4*)&b2[tx * 8 + 4];
#pragma unroll
    for (int i = 0; i < 7; i++) {
        int m = ty * 7 + i;
        float r[8];
#pragma unroll
        for (int j = 0; j < 4; j++) { UPK2(r[2 * j], r[2 * j + 1], accp[i][j]); }
        float4 v0 = make_float4(fmaxf(r[0] + bv0.x, 0.f), fmaxf(r[1] + bv0.y, 0.f),
                                fmaxf(r[2] + bv0.z, 0.f), fmaxf(r[3] + bv0.w, 0.f));
        float4 v1 = make_float4(fmaxf(r[4] + bv1.x, 0.f), fmaxf(r[5] + bv1.y, 0.f),
                                fmaxf(r[6] + bv1.z, 0.f), fmaxf(r[7] + bv1.w, 0.f));
        float* dst = &g_h2[((size_t)(b * HW2 + m)) * C2 + tx * 8];
        *(float4*)dst = v0;
        *(float4*)(dst + 4) = v1;
    }
#undef D2_PARAMS
#undef D2_PRODUCE
}

// ---------------- fc1 GEMM: BM=128 BN=64 BK=16, 256 thr, 8x4 tile, f32x2 ----------------
__global__ void __launch_bounds__(256) k_gemm1(int lda, int k_chunk, int k_iters) {
    const float* __restrict__ A  = g_h2;
    const float* __restrict__ Bw = g_fw1r;
    __shared__ __align__(16) float As[2][16][132];
    __shared__ __align__(16) float Bs[2][16][68];
    int m0 = blockIdx.x * 128, n0 = blockIdx.y * 64;
    int kbase = blockIdx.z * k_chunk;
    int tid = threadIdx.x;
    int ty = tid >> 4, tx = tid & 15;
    int am = tid >> 2, aq = tid & 3;
    const float* Ap0 = &A[(size_t)(m0 + am)      * lda + kbase + aq * 4];
    const float* Ap1 = &A[(size_t)(m0 + am + 64) * lda + kbase + aq * 4];
    const float* Bp  = &Bw[(size_t)(n0 + am)     * lda + kbase + aq * 4];
    unsigned long long accp[4][4];
#pragma unroll
    for (int i = 0; i < 4; i++)
#pragma unroll
        for (int j = 0; j < 4; j++) accp[i][j] = 0ull;

    float4 va0 = *(const float4*)Ap0;
    float4 va1 = *(const float4*)Ap1;
    float4 vb  = *(const float4*)Bp;
#pragma unroll 1
    for (int t = 0; t < k_iters; t++) {
        int cur = t & 1;
        As[cur][aq * 4 + 0][am] = va0.x; As[cur][aq * 4 + 1][am] = va0.y;
        As[cur][aq * 4 + 2][am] = va0.z; As[cur][aq * 4 + 3][am] = va0.w;
        As[cur][aq * 4 + 0][am + 64] = va1.x; As[cur][aq * 4 + 1][am + 64] = va1.y;
        As[cur][aq * 4 + 2][am + 64] = va1.z; As[cur][aq * 4 + 3][am + 64] = va1.w;
        Bs[cur][aq * 4 + 0][am] = vb.x; Bs[cur][aq * 4 + 1][am] = vb.y;
        Bs[cur][aq * 4 + 2][am] = vb.z; Bs[cur][aq * 4 + 3][am] = vb.w;
        __syncthreads();
        if (t + 1 < k_iters) {
            va0 = *(const float4*)(Ap0 + (t + 1) * 16);
            va1 = *(const float4*)(Ap1 + (t + 1) * 16);
            vb  = *(const float4*)(Bp  + (t + 1) * 16);
        }
#pragma unroll
        for (int k = 0; k < 16; k++) {
            float4 a0 = *(const float4*)&As[cur][k][ty * 8];
            float4 a1 = *(const float4*)&As[cur][k][ty * 8 + 4];
            float4 b0 = *(const float4*)&Bs[cur][k][tx * 4];
            unsigned long long ap[4], bp[4];
            PK2(ap[0], a0.x, a0.y); PK2(ap[1], a0.z, a0.w);
            PK2(ap[2], a1.x, a1.y); PK2(ap[3], a1.z, a1.w);
            PK2(bp[0], b0.x, b0.x); PK2(bp[1], b0.y, b0.y);
            PK2(bp[2], b0.z, b0.z); PK2(bp[3], b0.w, b0.w);
#pragma unroll
            for (int i = 0; i < 4; i++)
#pragma unroll
                for (int j = 0; j < 4; j++) FMA2(accp[i][j], ap[i], bp[j]);
        }
        if (t + 1 < k_iters) __syncthreads();
    }

    float r[8][4];
#pragma unroll
    for (int p = 0; p < 4; p++)
#pragma unroll
        for (int j = 0; j < 4; j++) {
            float lo, hi;
            UPK2(lo, hi, accp[p][j]);
            r[2 * p][j] = lo; r[2 * p + 1][j] = hi;
        }
#pragma unroll
    for (int i = 0; i < 8; i++) {
        int m = m0 + ty * 8 + i;
        float4 v = make_float4(r[i][0], r[i][1], r[i][2], r[i][3]);
        *(float4*)&g_a1p[((size_t)blockIdx.z * NB + m) * FCN + n0 + tx * 4] = v;
    }
}

// ---------------- reduce split-K + bias + relu ----------------
__global__ void __launch_bounds__(256) k_fc1fin(const float* __restrict__ fb1) {
    int t = blockIdx.x * blockDim.x + threadIdx.x;
    if (t >= NB * FCN) return;
    int n = t & (FCN - 1);
    float s = fb1[n];
#pragma unroll
    for (int z = 0; z < SPLITK; z++) s += g_a1p[(size_t)z * NB * FCN + t];
    g_a1[t] = fmaxf(s, 0.f);
}

// ---------------- fc2 ----------------
__global__ void __launch_bounds__(256) k_fc2(const float* __restrict__ fw2,
                                             const float* __restrict__ fb2,
                                             float* __restrict__ out) {
    int t = blockIdx.x * blockDim.x + threadIdx.x;
    if (t >= NB * 10) return;
    int b = t / 10, o = t % 10;
    float s = fb2[o];
    const float* a = &g_a1[(size_t)b * FCN];
    const float* w = &fw2[(size_t)o * FCN];
#pragma unroll 16
    for (int j = 0; j < FCN; j++) s += a[j] * w[j];
    out[t] = s;
}

// ---------------- launch ----------------
extern "C" void kernel_launch(void* const* d_in, const int* in_sizes, int n_in,
                              void* d_out, int out_size) {
    const float* x   = (const float*)d_in[0];
    const float* ow1 = (const float*)d_in[1];
    const float* ob1 = (const float*)d_in[2];
    const float* w1  = (const float*)d_in[3];
    const float* b1  = (const float*)d_in[4];
    const float* ow2 = (const float*)d_in[5];
    const float* ob2 = (const float*)d_in[6];
    const float* w2  = (const float*)d_in[7];
    const float* b2  = (const float*)d_in[8];
    const float* fw1 = (const float*)d_in[9];
    const float* fb1 = (const float*)d_in[10];
    const float* fw2 = (const float*)d_in[11];
    const float* fb2 = (const float*)d_in[12];
    float* out = (float*)d_out;
    (void)in_sizes; (void)n_in; (void)out_size;

    static int configured = 0;
    if (!configured) {
        cudaFuncSetAttribute(k_deform2, cudaFuncAttributeMaxDynamicSharedMemorySize, D2_SMEM);
        configured = 1;
    }

    k_prep_w2<<<(9 * C1 * C2 + 255) / 256, 256>>>(w2);
    k_prep_fw1<<<dim3(FCN, 2), 256>>>(fw1);
    k_deform1<<<NB, 224>>>(x, ow1, ob1, w1, b1);
    k_offset2<<<NB, 192>>>(ow2, ob2);
    k_deform2<<<NB, 224, D2_SMEM>>>(b2);
    k_gemm1<<<dim3(8, 2, SPLITK), 256>>>(FCK, KCHUNK, KCHUNK / 16);
    k_fc1fin<<<(NB * FCN) / 256, 256>>>(fb1);
    k_fc2<<<(NB * 10 + 255) / 256, 256>>>(fw2, fb2, out);
}

// round 13
// speedup vs baseline: 1.4340x; 1.0848x over previous
#include <cuda_runtime.h>
#include <cstdint>

// ---------------- problem constants ----------------
#define NB   1024
#define H1   28
#define W1   28
#define HW1  784
#define H2   14
#define W2c  14
#define HW2  196
#define C1   32
#define C2   64
#define K2D  288      // 32*9
#define FCK  12544    // 64*196
#define FCN  128
#define SPLITK 16
#define KCHUNK 784

// ---------------- f32x2 packed math ----------------
#define PK2(d, x, y)  asm("mov.b64 %0, {%1,%2};" : "=l"(d) : "f"(x), "f"(y))
#define UPK2(x, y, d) asm("mov.b64 {%0,%1}, %2;" : "=f"(x), "=f"(y) : "l"(d))
#define FMA2(c, a, b) asm("fma.rn.f32x2 %0, %1, %2, %0;" : "+l"(c) : "l"(a), "l"(b))

// ---------------- device scratch ----------------
__device__ float g_h1  [(size_t)NB * C1 * HW2];
__device__ float g_off2[(size_t)NB * 18 * HW2];
__device__ float g_w2k [9 * C1 * C2];                    // [kt][c][n]
__device__ float g_fw1r[(size_t)FCN * FCK];              // [n][hw*64+c]
__device__ float g_h2  [(size_t)NB * HW2 * C2];          // [(b*196+hw)][c]  (m-major)
__device__ float g_a1p [(size_t)SPLITK * NB * FCN];
__device__ float g_a1  [(size_t)NB * FCN];

// deform2 dynamic smem: sh1(32*197) + 2*ss(32*197) + 2*sw(32*68)
#define D2_F32S (32 * 197 + 2 * 32 * 197 + 2 * 32 * 68)
#define D2_SMEM (D2_F32S * 4)

// k_offset2 tile geometry: 16x16 zero-padded tile, row stride 17 (bank-conflict-free)
#define O2_RS   17
#define O2_CS   (16 * O2_RS)   // 272 floats per channel

// ---------------- helpers ----------------
__device__ __forceinline__ float bilin(const float* __restrict__ img, int H, int W,
                                       float py, float px) {
    float y0f = floorf(py), x0f = floorf(px);
    int y0 = (int)y0f, x0 = (int)x0f;
    float wy1 = py - y0f, wx1 = px - x0f;
    float wy0 = 1.f - wy1, wx0 = 1.f - wx1;
    bool yv0 = (y0 >= 0) && (y0 < H);
    bool yv1 = (y0 >= -1) && (y0 < H - 1);
    bool xv0 = (x0 >= 0) && (x0 < W);
    bool xv1 = (x0 >= -1) && (x0 < W - 1);
    int yc0 = min(max(y0, 0), H - 1),   yc1 = min(max(y0 + 1, 0), H - 1);
    int xc0 = min(max(x0, 0), W - 1),   xc1 = min(max(x0 + 1, 0), W - 1);
    float v = 0.f;
    v += (yv0 && xv0) ? wy0 * wx0 * img[yc0 * W + xc0] : 0.f;
    v += (yv0 && xv1) ? wy0 * wx1 * img[yc0 * W + xc1] : 0.f;
    v += (yv1 && xv0) ? wy1 * wx0 * img[yc1 * W + xc0] : 0.f;
    v += (yv1 && xv1) ? wy1 * wx1 * img[yc1 * W + xc1] : 0.f;
    return v;
}

// ---------------- K0a: w2 rearrange ----------------
__global__ void k_prep_w2(const float* __restrict__ w2) {
    int t = blockIdx.x * blockDim.x + threadIdx.x;
    if (t < 9 * C1 * C2) {
        int kt = t / (C1 * C2), r = t % (C1 * C2), c = r / C2, n = r % C2;
        g_w2k[t] = w2[n * K2D + c * 9 + kt];
    }
}

// ---------------- K0b: fw1 transpose (coalesced both sides via smem tile) ----------------
__global__ void __launch_bounds__(256) k_prep_fw1(const float* __restrict__ fw1) {
    __shared__ float st[64 * 99];
    int n = blockIdx.x, h0 = blockIdx.y * 98;
    for (int i = threadIdx.x; i < 64 * 98; i += 256) {
        int c = i / 98, hwl = i % 98;
        st[c * 99 + hwl] = fw1[(size_t)n * FCK + c * HW2 + h0 + hwl];
    }
    __syncthreads();
    for (int j = threadIdx.x; j < 98 * 64; j += 256) {
        int hwl = j / 64, c = j % 64;
        g_fw1r[(size_t)n * FCK + (h0 + hwl) * 64 + c] = st[c * 99 + hwl];
    }
}

// ---------------- K1: fused offset-conv1 + deform-conv1 + relu + pool ----------------
__global__ void __launch_bounds__(224) k_deform1(const float* __restrict__ x,
                                                 const float* __restrict__ ow1,
                                                 const float* __restrict__ ob1,
                                                 const float* __restrict__ w1,
                                                 const float* __restrict__ b1) {
    int b = blockIdx.x;
    __shared__ float sx[HW1];
    __shared__ float sow[162];
    __shared__ float sob[18];
    __shared__ float swt[C1 * 9];
    __shared__ float sb[C1];
    for (int i = threadIdx.x; i < HW1; i += 224) sx[i] = x[(size_t)b * HW1 + i];
    if (threadIdx.x < 162) sow[threadIdx.x] = ow1[threadIdx.x];
    if (threadIdx.x < 18)  sob[threadIdx.x] = ob1[threadIdx.x];
    for (int i = threadIdx.x; i < C1 * 9; i += 224) swt[i] = w1[i];
    if (threadIdx.x < C1) sb[threadIdx.x] = b1[threadIdx.x];
    __syncthreads();
    int t = threadIdx.x;
    if (t >= HW2) return;
    int ph = t / W2c, pw = t % W2c;
    float acc[C1];
#pragma unroll
    for (int o = 0; o < C1; o++) acc[o] = 0.f;
#pragma unroll 1
    for (int s4 = 0; s4 < 4; s4++) {
        int y = ph * 2 + (s4 >> 1), w = pw * 2 + (s4 & 1);
        float p[9];
#pragma unroll
        for (int ky = 0; ky < 3; ky++)
#pragma unroll
            for (int kx = 0; kx < 3; kx++) {
                int y2 = y + ky - 1, x2 = w + kx - 1;
                bool ok = (y2 >= 0) && (y2 < H1) && (x2 >= 0) && (x2 < W1);
                p[ky * 3 + kx] = ok ? sx[y2 * W1 + x2] : 0.f;
            }
        float s[9];
#pragma unroll
        for (int k = 0; k < 9; k++) {
            float dy = sob[2 * k], dx = sob[2 * k + 1];
#pragma unroll
            for (int j = 0; j < 9; j++) {
                dy += sow[(2 * k) * 9 + j] * p[j];
                dx += sow[(2 * k + 1) * 9 + j] * p[j];
            }
            int ky = k / 3, kx = k % 3;
            s[k] = bilin(sx, H1, W1, dy + (float)(y - 1 + ky), dx + (float)(w - 1 + kx));
        }
#pragma unroll
        for (int o = 0; o < C1; o++) {
            float v = sb[o];
#pragma unroll
            for (int k = 0; k < 9; k++) v += swt[o * 9 + k] * s[k];
            acc[o] += fmaxf(v, 0.f);
        }
    }
#pragma unroll
    for (int o = 0; o < C1; o++)
        g_h1[((size_t)b * C1 + o) * HW2 + t] = acc[o] * 0.25f;
}

// ---------------- K2: offset conv2 (stride-17 padded tiles: conflict-free) ------
__global__ void __launch_bounds__(192) k_offset2(const float* __restrict__ ow2,
                                                 const float* __restrict__ ob2) {
    int b = blockIdx.x;
    __shared__ float sh[16 * O2_CS];
    __shared__ float sw[18 * 144];
    int t = threadIdx.x;
    bool act = t < 168;
    int og = t / 28, pg = t % 28;
    int y = pg >> 1, x0 = (pg & 1) * 7;
    int o0 = og * 3;
    float acc[3][7];
    if (act) {
#pragma unroll
        for (int q = 0; q < 3; q++) {
            float bv = ob2[o0 + q];
#pragma unroll
            for (int p = 0; p < 7; p++) acc[q][p] = bv;
        }
    }
#pragma unroll 1
    for (int half = 0; half < 2; half++) {
        if (half) __syncthreads();
        // zero borders of each 16x16 tile (row stride 17)
        for (int i = t; i < 16 * 60; i += 192) {
            int c = i / 60, e = i % 60;
            int py, px;
            if (e < 16)      { py = 0;  px = e; }
            else if (e < 32) { py = 15; px = e - 16; }
            else { int e2 = e - 32; py = 1 + (e2 >> 1); px = (e2 & 1) * 15; }
            sh[c * O2_CS + py * O2_RS + px] = 0.f;
        }
        // interior fill
        for (int i = t; i < 16 * HW2; i += 192) {
            int c = i / HW2, hw = i % HW2, yy = hw / W2c, xx = hw % W2c;
            sh[c * O2_CS + (yy + 1) * O2_RS + (xx + 1)] =
                g_h1[(size_t)b * (C1 * HW2) + (half * 16 + c) * HW2 + hw];
        }
        // weights for this half
        for (int i = t; i < 18 * 144; i += 192) {
            int o = i / 144, r = i % 144, cl = r / 9, kt = r % 9;
            sw[i] = ow2[o * K2D + (half * 16 + cl) * 9 + kt];
        }
        __syncthreads();
        if (act) {
#pragma unroll 1
            for (int c = 0; c < 16; c++) {
                const float* base = &sh[c * O2_CS + y * O2_RS + x0];
                float nb[27];
#pragma unroll
                for (int dy = 0; dy < 3; dy++)
#pragma unroll
                    for (int dx = 0; dx < 9; dx++)
                        nb[dy * 9 + dx] = base[dy * O2_RS + dx];
#pragma unroll
                for (int kt = 0; kt < 9; kt++) {
                    int ky = kt / 3, kx = kt % 3;
                    float w0 = sw[(o0 + 0) * 144 + c * 9 + kt];
                    float w1v = sw[(o0 + 1) * 144 + c * 9 + kt];
                    float w2v = sw[(o0 + 2) * 144 + c * 9 + kt];
#pragma unroll
                    for (int p = 0; p < 7; p++) {
                        float v = nb[ky * 9 + kx + p];
                        acc[0][p] += w0 * v;
                        acc[1][p] += w1v * v;
                        acc[2][p] += w2v * v;
                    }
                }
            }
        }
    }
    if (act) {
#pragma unroll
        for (int q = 0; q < 3; q++)
#pragma unroll
            for (int p = 0; p < 7; p++)
                g_off2[((size_t)b * 18 + o0 + q) * HW2 + y * W2c + x0 + p] = acc[q][p];
    }
}

// ---------------- K3: FUSED sampling + deform2 GEMM (v6) -------------------
__global__ void __launch_bounds__(224) k_deform2(const float* __restrict__ b2) {
    extern __shared__ float dsm[];
    float* sh1 = dsm;                       // 32 x 197
    float* ss  = dsm + 32 * 197;            // 2 x (32 x 197)
    float* sw  = dsm + 3 * 32 * 197;        // 2 x (32 x 68)
    int b = blockIdx.x;
    int tid = threadIdx.x;
    for (int i = tid; i < C1 * HW2; i += 224) {
        int c = i / HW2, hw = i % HW2;
        sh1[c * 197 + hw] = g_h1[(size_t)b * (C1 * HW2) + i];
    }
    int ty = tid >> 3, tx = tid & 7;
    bool samp_act = tid < HW2;
    int shw = tid, sy = shw / W2c, sx = shw % W2c;

    unsigned long long accp[7][4];
#pragma unroll
    for (int i = 0; i < 7; i++)
#pragma unroll
        for (int j = 0; j < 4; j++) accp[i][j] = 0ull;

    float w00 = 0.f, w01 = 0.f, w10 = 0.f, w11 = 0.f;
    int i00 = 0, i01 = 0, i10 = 0, i11 = 0;
#define D2_PARAMS(KT)                                                          \
    if (samp_act) {                                                            \
        int ky = (KT) / 3, kx = (KT) % 3;                                      \
        float dy = g_off2[((size_t)b * 18 + 2 * (KT))     * HW2 + shw];        \
        float dx = g_off2[((size_t)b * 18 + 2 * (KT) + 1) * HW2 + shw];        \
        float py = dy + (float)(sy - 1 + ky);                                  \
        float px = dx + (float)(sx - 1 + kx);                                  \
        float y0f = floorf(py), x0f = floorf(px);                              \
        int y0 = (int)y0f, x0 = (int)x0f;                                      \
        float wy1 = py - y0f, wx1 = px - x0f;                                  \
        float wy0 = 1.f - wy1, wx0 = 1.f - wx1;                                \
        bool yv0 = (y0 >= 0) && (y0 < H2), yv1 = (y0 >= -1) && (y0 < H2 - 1);  \
        bool xv0 = (x0 >= 0) && (x0 < W2c), xv1 = (x0 >= -1) && (x0 < W2c - 1);\
        int yc0 = min(max(y0, 0), H2 - 1),  yc1 = min(max(y0 + 1, 0), H2 - 1); \
        int xc0 = min(max(x0, 0), W2c - 1), xc1 = min(max(x0 + 1, 0), W2c - 1);\
        w00 = (yv0 && xv0) ? wy0 * wx0 : 0.f;                                  \
        w01 = (yv0 && xv1) ? wy0 * wx1 : 0.f;                                  \
        w10 = (yv1 && xv0) ? wy1 * wx0 : 0.f;                                  \
        w11 = (yv1 && xv1) ? wy1 * wx1 : 0.f;                                  \
        i00 = yc0 * W2c + xc0; i01 = yc0 * W2c + xc1;                          \
        i10 = yc1 * W2c + xc0; i11 = yc1 * W2c + xc1;                          \
    }
#define D2_PRODUCE(KT, BUF)                                                    \
    {                                                                          \
        float* ssb = ss + (BUF) * (32 * 197);                                  \
        if (samp_act) {                                                        \
            _Pragma("unroll 4")                                                \
            for (int c = 0; c < C1; c++) {                                     \
                const float* im = &sh1[c * 197];                               \
                ssb[c * 197 + shw] =                                           \
                    w00 * im[i00] + w01 * im[i01] + w10 * im[i10] + w11 * im[i11]; \
            }                                                                  \
        }                                                                      \
        float* swb = sw + (BUF) * (32 * 68);                                   \
        for (int i = tid; i < C1 * C2; i += 224)                               \
            swb[(i >> 6) * 68 + (i & 63)] = g_w2k[(KT) * (C1 * C2) + i];       \
    }

    // prologue
    D2_PARAMS(0)
    __syncthreads();            // sh1 ready
    D2_PRODUCE(0, 0)
    __syncthreads();            // buffer 0 ready

#pragma unroll 1
    for (int kt = 0; kt < 9; kt++) {
        int cur = kt & 1;
        if (kt < 8) {
            D2_PARAMS(kt + 1)
            D2_PRODUCE(kt + 1, cur ^ 1)   // overlaps with GEMM below via other warps
        }
        const float* ssb = ss + cur * (32 * 197);
        const float* swb = sw + cur * (32 * 68);
#pragma unroll 4
        for (int c = 0; c < C1; c++) {
            float a[7];
#pragma unroll
            for (int i = 0; i < 7; i++) a[i] = ssb[c * 197 + ty * 7 + i];
            float4 b0 = *(const float4*)&swb[c * 68 + tx * 8];
            float4 b1 = *(const float4*)&swb[c * 68 + tx * 8 + 4];
            unsigned long long bp[4], ap;
            PK2(bp[0], b0.x, b0.y); PK2(bp[1], b0.z, b0.w);
            PK2(bp[2], b1.x, b1.y); PK2(bp[3], b1.z, b1.w);
#pragma unroll
            for (int i = 0; i < 7; i++) {
                PK2(ap, a[i], a[i]);
#pragma unroll
                for (int j = 0; j < 4; j++) FMA2(accp[i][j], ap, bp[j]);
            }
        }
        if (kt < 8) __syncthreads();
    }

    // epilogue: bias + relu, store m-major [m][64]
    float4 bv0 = *(const float4*)&b2[tx * 8];
    float4 bv1 = *(const float4*)&b2[tx * 8 + 4];
#pragma unroll
    for (int i = 0; i < 7; i++) {
        int m = ty * 7 + i;
        float r[8];
#pragma unroll
        for (int j = 0; j < 4; j++) { UPK2(r[2 * j], r[2 * j + 1], accp[i][j]); }
        float4 v0 = make_float4(fmaxf(r[0] + bv0.x, 0.f), fmaxf(r[1] + bv0.y, 0.f),
                                fmaxf(r[2] + bv0.z, 0.f), fmaxf(r[3] + bv0.w, 0.f));
        float4 v1 = make_float4(fmaxf(r[4] + bv1.x, 0.f), fmaxf(r[5] + bv1.y, 0.f),
                                fmaxf(r[6] + bv1.z, 0.f), fmaxf(r[7] + bv1.w, 0.f));
        float* dst = &g_h2[((size_t)(b * HW2 + m)) * C2 + tx * 8];
        *(float4*)dst = v0;
        *(float4*)(dst + 4) = v1;
    }
#undef D2_PARAMS
#undef D2_PRODUCE
}

// ---------------- fc1 GEMM: BM=128 BN=64 BK=16, 256 thr, 8x4 tile, f32x2 ----------------
__global__ void __launch_bounds__(256) k_gemm1(int lda, int k_chunk, int k_iters) {
    const float* __restrict__ A  = g_h2;
    const float* __restrict__ Bw = g_fw1r;
    __shared__ __align__(16) float As[2][16][132];
    __shared__ __align__(16) float Bs[2][16][68];
    int m0 = blockIdx.x * 128, n0 = blockIdx.y * 64;
    int kbase = blockIdx.z * k_chunk;
    int tid = threadIdx.x;
    int ty = tid >> 4, tx = tid & 15;
    int am = tid >> 2, aq = tid & 3;
    const float* Ap0 = &A[(size_t)(m0 + am)      * lda + kbase + aq * 4];
    const float* Ap1 = &A[(size_t)(m0 + am + 64) * lda + kbase + aq * 4];
    const float* Bp  = &Bw[(size_t)(n0 + am)     * lda + kbase + aq * 4];
    unsigned long long accp[4][4];
#pragma unroll
    for (int i = 0; i < 4; i++)
#pragma unroll
        for (int j = 0; j < 4; j++) accp[i][j] = 0ull;

    float4 va0 = *(const float4*)Ap0;
    float4 va1 = *(const float4*)Ap1;
    float4 vb  = *(const float4*)Bp;
#pragma unroll 1
    for (int t = 0; t < k_iters; t++) {
        int cur = t & 1;
        As[cur][aq * 4 + 0][am] = va0.x; As[cur][aq * 4 + 1][am] = va0.y;
        As[cur][aq * 4 + 2][am] = va0.z; As[cur][aq * 4 + 3][am] = va0.w;
        As[cur][aq * 4 + 0][am + 64] = va1.x; As[cur][aq * 4 + 1][am + 64] = va1.y;
        As[cur][aq * 4 + 2][am + 64] = va1.z; As[cur][aq * 4 + 3][am + 64] = va1.w;
        Bs[cur][aq * 4 + 0][am] = vb.x; Bs[cur][aq * 4 + 1][am] = vb.y;
        Bs[cur][aq * 4 + 2][am] = vb.z; Bs[cur][aq * 4 + 3][am] = vb.w;
        __syncthreads();
        if (t + 1 < k_iters) {
            va0 = *(const float4*)(Ap0 + (t + 1) * 16);
            va1 = *(const float4*)(Ap1 + (t + 1) * 16);
            vb  = *(const float4*)(Bp  + (t + 1) * 16);
        }
#pragma unroll
        for (int k = 0; k < 16; k++) {
            float4 a0 = *(const float4*)&As[cur][k][ty * 8];
            float4 a1 = *(const float4*)&As[cur][k][ty * 8 + 4];
            float4 b0 = *(const float4*)&Bs[cur][k][tx * 4];
            unsigned long long ap[4], bp[4];
            PK2(ap[0], a0.x, a0.y); PK2(ap[1], a0.z, a0.w);
            PK2(ap[2], a1.x, a1.y); PK2(ap[3], a1.z, a1.w);
            PK2(bp[0], b0.x, b0.x); PK2(bp[1], b0.y, b0.y);
            PK2(bp[2], b0.z, b0.z); PK2(bp[3], b0.w, b0.w);
#pragma unroll
            for (int i = 0; i < 4; i++)
#pragma unroll
                for (int j = 0; j < 4; j++) FMA2(accp[i][j], ap[i], bp[j]);
        }
        if (t + 1 < k_iters) __syncthreads();
    }

    float r[8][4];
#pragma unroll
    for (int p = 0; p < 4; p++)
#pragma unroll
        for (int j = 0; j < 4; j++) {
            float lo, hi;
            UPK2(lo, hi, accp[p][j]);
            r[2 * p][j] = lo; r[2 * p + 1][j] = hi;
        }
#pragma unroll
    for (int i = 0; i < 8; i++) {
        int m = m0 + ty * 8 + i;
        float4 v = make_float4(r[i][0], r[i][1], r[i][2], r[i][3]);
        *(float4*)&g_a1p[((size_t)blockIdx.z * NB + m) * FCN + n0 + tx * 4] = v;
    }
}

// ---------------- reduce split-K + bias + relu ----------------
__global__ void __launch_bounds__(256) k_fc1fin(const float* __restrict__ fb1) {
    int t = blockIdx.x * blockDim.x + threadIdx.x;
    if (t >= NB * FCN) return;
    int n = t & (FCN - 1);
    float s = fb1[n];
#pragma unroll
    for (int z = 0; z < SPLITK; z++) s += g_a1p[(size_t)z * NB * FCN + t];
    g_a1[t] = fmaxf(s, 0.f);
}

// ---------------- fc2 ----------------
__global__ void __launch_bounds__(256) k_fc2(const float* __restrict__ fw2,
                                             const float* __restrict__ fb2,
                                             float* __restrict__ out) {
    int t = blockIdx.x * blockDim.x + threadIdx.x;
    if (t >= NB * 10) return;
    int b = t / 10, o = t % 10;
    float s = fb2[o];
    const float* a = &g_a1[(size_t)b * FCN];
    const float* w = &fw2[(size_t)o * FCN];
#pragma unroll 16
    for (int j = 0; j < FCN; j++) s += a[j] * w[j];
    out[t] = s;
}

// ---------------- launch ----------------
extern "C" void kernel_launch(void* const* d_in, const int* in_sizes, int n_in,
                              void* d_out, int out_size) {
    const float* x   = (const float*)d_in[0];
    const float* ow1 = (const float*)d_in[1];
    const float* ob1 = (const float*)d_in[2];
    const float* w1  = (const float*)d_in[3];
    const float* b1  = (const float*)d_in[4];
    const float* ow2 = (const float*)d_in[5];
    const float* ob2 = (const float*)d_in[6];
    const float* w2  = (const float*)d_in[7];
    const float* b2  = (const float*)d_in[8];
    const float* fw1 = (const float*)d_in[9];
    const float* fb1 = (const float*)d_in[10];
    const float* fw2 = (const float*)d_in[11];
    const float* fb2 = (const float*)d_in[12];
    float* out = (float*)d_out;
    (void)in_sizes; (void)n_in; (void)out_size;

    static int configured = 0;
    if (!configured) {
        cudaFuncSetAttribute(k_deform2, cudaFuncAttributeMaxDynamicSharedMemorySize, D2_SMEM);
        configured = 1;
    }

    k_prep_w2<<<(9 * C1 * C2 + 255) / 256, 256>>>(w2);
    k_prep_fw1<<<dim3(FCN, 2), 256>>>(fw1);
    k_deform1<<<NB, 224>>>(x, ow1, ob1, w1, b1);
    k_offset2<<<NB, 192>>>(ow2, ob2);
    k_deform2<<<NB, 224, D2_SMEM>>>(b2);
    k_gemm1<<<dim3(8, 2, SPLITK), 256>>>(FCK, KCHUNK, KCHUNK / 16);
    k_fc1fin<<<(NB * FCN) / 256, 256>>>(fb1);
    k_fc2<<<(NB * 10 + 255) / 256, 256>>>(fw2, fb2, out);
}